// round 2
// baseline (speedup 1.0000x reference)
#include <cuda_runtime.h>
#include <math.h>

#define NM 64
#define NA 24
#define NP 276
#define NPPAD 288
#define NT 6000
#define NTPAD 6016
#define QV 0.22360679774997896f   // sqrt(5)/sig
#define KE 0.016666666666666666f  // 5/(3*sig^2)

#define G1_BLOCKS 94              // ceil(6016/64) t-tiles of 64
#define G2_PT 5                   // p-tiles of 64 (276 -> 320 padded)
#define G2_KS 29                  // K splits
#define G2_CHUNK 208              // 13 k-tiles of 16
#define G2_PPAD 320

typedef unsigned long long u64;

// ---------------- static device scratch (no allocation) ----------------
__device__ float g_qxs[NM * NP];        // q*xs  [m][p]
__device__ float g_xs3[NM * NP];        // xs^3  [m][p]
__device__ float g_nq[NM];              // |qxs_m|^2
__device__ float g_qxsT[NPPAD * NM];    // q*xs transposed, zero-padded rows
__device__ float g_nt[NTPAD];           // q^2 |xst_t|^2
__device__ float g_ct[NTPAD];           // q * (xst_t . Jx_t)
__device__ float g_a[NM * NTPAD];       // q * exp_xs * dot
__device__ float g_b[NM * NTPAD];       // exp1
__device__ float g_Ep[G1_BLOCKS * NM];  // per-block E partials
__device__ float g_sa[G1_BLOCKS * NM];  // per-block sum_t a partials
__device__ float g_F2[G2_KS * NM * G2_PPAD]; // per-ksplit F partials

__device__ __forceinline__ void ffma2(u64& c, u64 a, u64 b) {
    asm("fma.rn.f32x2 %0, %1, %2, %0;" : "+l"(c) : "l"(a), "l"(b));
}
__device__ __forceinline__ float2 upk(u64 v) {
    float2 f;
    asm("mov.b64 {%0, %1}, %2;" : "=f"(f.x), "=f"(f.y) : "l"(v));
    return f;
}

__device__ __forceinline__ void pair_ij(int p, int& i, int& j) {
    int ii = (int)((1.0f + sqrtf(1.0f + 8.0f * (float)p)) * 0.5f);
    while (ii * (ii - 1) / 2 > p) ii--;
    while ((ii + 1) * ii / 2 <= p) ii++;
    i = ii;
    j = p - ii * (ii - 1) / 2;
}

// ---------------- prep1: descriptors per molecule ----------------
__global__ void prep1_kernel(const float* __restrict__ Rs) {
    __shared__ float red[288];
    int m = blockIdx.x;
    int p = threadIdx.x;   // 0..287
    float qv = 0.0f;
    if (p < NP) {
        int i, j;
        pair_ij(p, i, j);
        float dx = Rs[(m * NA + i) * 3 + 0] - Rs[(m * NA + j) * 3 + 0];
        float dy = Rs[(m * NA + i) * 3 + 1] - Rs[(m * NA + j) * 3 + 1];
        float dz = Rs[(m * NA + i) * 3 + 2] - Rs[(m * NA + j) * 3 + 2];
        float d = sqrtf(dx * dx + dy * dy + dz * dz);
        float xs = 1.0f / d;
        g_qxs[m * NP + p] = QV * xs;
        g_xs3[m * NP + p] = xs * xs * xs;
        qv = QV * xs;
    }
    g_qxsT[p * NM + m] = qv;   // zero rows for p >= NP
    red[p] = qv * qv;
    __syncthreads();
    if (p < 32) {
        float s = red[p];
        for (int k = p + 32; k < 288; k += 32) s += red[k];
        #pragma unroll
        for (int o = 16; o > 0; o >>= 1) s += __shfl_xor_sync(0xffffffffu, s, o);
        if (p == 0) g_nq[m] = s;
    }
}

// ---------------- prep2: per-training-point scalars ----------------
__global__ void prep2_kernel(const float* __restrict__ xt, const float* __restrict__ jx) {
    int w = (blockIdx.x * blockDim.x + threadIdx.x) >> 5;
    int lane = threadIdx.x & 31;
    if (w >= NTPAD) return;
    if (w >= NT) {
        if (lane == 0) { g_nt[w] = 0.0f; g_ct[w] = 0.0f; }
        return;
    }
    const float* xr = xt + (size_t)w * NP;
    const float* jr = jx + (size_t)w * NP;
    float sn = 0.0f, sc = 0.0f;
    #pragma unroll
    for (int k = 0; k < 9; k++) {
        int p = lane + 32 * k;
        if (p < NP) {
            float x = xr[p];
            sn = fmaf(x, x, sn);
            sc = fmaf(x, jr[p], sc);
        }
    }
    #pragma unroll
    for (int o = 16; o > 0; o >>= 1) {
        sn += __shfl_xor_sync(0xffffffffu, sn, o);
        sc += __shfl_xor_sync(0xffffffffu, sc, o);
    }
    if (lane == 0) {
        g_nt[w] = QV * QV * sn;
        g_ct[w] = QV * sc;
    }
}

// ---------------- GEMM1: S1/S2 = qxs @ [xst; Jx]^T, fused transcendental epilogue ----------------
__global__ __launch_bounds__(256, 1)
void gemm1_kernel(const float* __restrict__ xt, const float* __restrict__ jx) {
    __shared__ float As[16 * 128];   // qxs duplicated: [k][2m]
    __shared__ float Bx[16 * 68];    // xst  [k][t]
    __shared__ float Bj[16 * 68];    // Jx   [k][t]

    const int tid = threadIdx.x;
    const int tx = tid & 15;         // t frag = t0 + 4*tx + {0..3}
    const int ty = tid >> 4;         // m frag = 4*ty + {0..3}
    const int t0 = blockIdx.x * 64;

    const int lak = tid >> 4, lam = tid & 15;  // A loader: row k, 4-col group
    const int lbt = tid >> 2, lbc = tid & 3;   // B loader: t row, k 4-group

    u64 acc1[4][2], acc2[4][2];
    #pragma unroll
    for (int i = 0; i < 4; i++) { acc1[i][0] = 0ull; acc1[i][1] = 0ull; acc2[i][0] = 0ull; acc2[i][1] = 0ull; }

    for (int kt = 0; kt < 18; kt++) {
        int k0 = kt * 16;
        // global loads
        float4 av = *(const float4*)&g_qxsT[(k0 + lak) * NM + 4 * lam];
        int kk = k0 + 4 * lbc;
        int tg = t0 + lbt;
        float4 xv = make_float4(0.f, 0.f, 0.f, 0.f);
        float4 jv = make_float4(0.f, 0.f, 0.f, 0.f);
        if (tg < NT && kk < NP) {
            xv = *(const float4*)&xt[(size_t)tg * NP + kk];
            jv = *(const float4*)&jx[(size_t)tg * NP + kk];
        }
        __syncthreads();
        // store A duplicated
        *(float4*)&As[lak * 128 + 8 * lam]     = make_float4(av.x, av.x, av.y, av.y);
        *(float4*)&As[lak * 128 + 8 * lam + 4] = make_float4(av.z, av.z, av.w, av.w);
        // store B transposed
        Bx[(4 * lbc + 0) * 68 + lbt] = xv.x;
        Bx[(4 * lbc + 1) * 68 + lbt] = xv.y;
        Bx[(4 * lbc + 2) * 68 + lbt] = xv.z;
        Bx[(4 * lbc + 3) * 68 + lbt] = xv.w;
        Bj[(4 * lbc + 0) * 68 + lbt] = jv.x;
        Bj[(4 * lbc + 1) * 68 + lbt] = jv.y;
        Bj[(4 * lbc + 2) * 68 + lbt] = jv.z;
        Bj[(4 * lbc + 3) * 68 + lbt] = jv.w;
        __syncthreads();

        #pragma unroll
        for (int k = 0; k < 16; k++) {
            ulonglong2 A01 = *(const ulonglong2*)&As[k * 128 + 8 * ty];
            ulonglong2 A23 = *(const ulonglong2*)&As[k * 128 + 8 * ty + 4];
            ulonglong2 X  = *(const ulonglong2*)&Bx[k * 68 + 4 * tx];
            ulonglong2 J  = *(const ulonglong2*)&Bj[k * 68 + 4 * tx];
            ffma2(acc1[0][0], A01.x, X.x); ffma2(acc1[0][1], A01.x, X.y);
            ffma2(acc1[1][0], A01.y, X.x); ffma2(acc1[1][1], A01.y, X.y);
            ffma2(acc1[2][0], A23.x, X.x); ffma2(acc1[2][1], A23.x, X.y);
            ffma2(acc1[3][0], A23.y, X.x); ffma2(acc1[3][1], A23.y, X.y);
            ffma2(acc2[0][0], A01.x, J.x); ffma2(acc2[0][1], A01.x, J.y);
            ffma2(acc2[1][0], A01.y, J.x); ffma2(acc2[1][1], A01.y, J.y);
            ffma2(acc2[2][0], A23.x, J.x); ffma2(acc2[2][1], A23.x, J.y);
            ffma2(acc2[3][0], A23.y, J.x); ffma2(acc2[3][1], A23.y, J.y);
        }
    }

    // fused epilogue: sq -> a, b; store g_a, g_b; local E/sa partials
    const int m0 = ty * 4;
    const int tb = t0 + 4 * tx;
    float ntv[4], ctv[4];
    #pragma unroll
    for (int i = 0; i < 4; i++) { ntv[i] = g_nt[tb + i]; ctv[i] = g_ct[tb + i]; }

    float eloc[4], saloc[4];
    #pragma unroll
    for (int mi = 0; mi < 4; mi++) {
        float nqv = g_nq[m0 + mi];
        float s1v[4], s2v[4];
        float2 u;
        u = upk(acc1[mi][0]); s1v[0] = u.x; s1v[1] = u.y;
        u = upk(acc1[mi][1]); s1v[2] = u.x; s1v[3] = u.y;
        u = upk(acc2[mi][0]); s2v[0] = u.x; s2v[1] = u.y;
        u = upk(acc2[mi][1]); s2v[2] = u.x; s2v[3] = u.y;
        float oa[4], ob[4];
        float el = 0.0f, sl = 0.0f;
        #pragma unroll
        for (int j = 0; j < 4; j++) {
            float sq = fmaf(-2.0f * QV, s1v[j], nqv + ntv[j]);
            float xd = sqrtf(fmaxf(sq, 0.0f));
            float e  = KE * __expf(-xd);
            float dt = s2v[j] - ctv[j];
            float a  = e * dt;
            float b  = fmaf(e, xd, e);      // e*(1+xd)
            oa[j] = QV * a;
            ob[j] = b;
            el = fmaf(b, dt, el);
            sl += a;
        }
        eloc[mi] = el; saloc[mi] = sl;
        *(float4*)&g_a[(m0 + mi) * NTPAD + tb] = make_float4(oa[0], oa[1], oa[2], oa[3]);
        *(float4*)&g_b[(m0 + mi) * NTPAD + tb] = make_float4(ob[0], ob[1], ob[2], ob[3]);
    }

    // deterministic per-block reduction of E and sa (reuse As smem)
    __syncthreads();
    float* Es = As;           // 1024 floats
    float* Ss = As + 1024;    // 1024 floats
    #pragma unroll
    for (int mi = 0; mi < 4; mi++) {
        Es[(m0 + mi) * 16 + tx] = eloc[mi];
        Ss[(m0 + mi) * 16 + tx] = saloc[mi];
    }
    __syncthreads();
    if (tid < 64) {
        float se = 0.0f, ss = 0.0f;
        #pragma unroll
        for (int x = 0; x < 16; x++) { se += Es[tid * 16 + x]; ss += Ss[tid * 16 + x]; }
        g_Ep[blockIdx.x * NM + tid] = se;
        g_sa[blockIdx.x * NM + tid] = ss;
    }
}

// ---------------- GEMM2: F2 = -( (q a) @ xst + b @ Jx ), K-split ----------------
__global__ __launch_bounds__(256, 1)
void gemm2_kernel(const float* __restrict__ xt, const float* __restrict__ jx) {
    __shared__ float Aa[16 * 128];   // q*a duplicated [k][2m]
    __shared__ float Ab[16 * 128];   // b duplicated
    __shared__ float Bx[16 * 64];    // xst [k][p]
    __shared__ float Bj[16 * 64];    // Jx  [k][p]

    const int tid = threadIdx.x;
    const int tx = tid & 15;         // p frag = p0 + 4*tx + {0..3}
    const int ty = tid >> 4;         // m frag = 4*ty + {0..3}
    const int p0 = blockIdx.x * 64;
    const int t0 = blockIdx.y * G2_CHUNK;

    const int lam = tid >> 2, lac = tid & 3;   // A loader: m row, k 4-group
    const int lbk = tid >> 4, lbc = tid & 15;  // B loader: k row, p 4-group

    u64 acc[4][2];
    #pragma unroll
    for (int i = 0; i < 4; i++) { acc[i][0] = 0ull; acc[i][1] = 0ull; }

    for (int kt = 0; kt < 13; kt++) {
        int tt0 = t0 + kt * 16;
        // A loads (t contiguous)
        int ta = tt0 + 4 * lac;
        float4 av = make_float4(0.f, 0.f, 0.f, 0.f);
        float4 bv = make_float4(0.f, 0.f, 0.f, 0.f);
        if (ta < NT) {
            av = *(const float4*)&g_a[lam * NTPAD + ta];
            bv = *(const float4*)&g_b[lam * NTPAD + ta];
        }
        // B loads (p contiguous)
        int tg = tt0 + lbk;
        int pc = p0 + 4 * lbc;
        float4 xv = make_float4(0.f, 0.f, 0.f, 0.f);
        float4 jv = make_float4(0.f, 0.f, 0.f, 0.f);
        if (tg < NT && pc < NP) {
            xv = *(const float4*)&xt[(size_t)tg * NP + pc];
            jv = *(const float4*)&jx[(size_t)tg * NP + pc];
        }
        __syncthreads();
        // store A transposed + duplicated
        #pragma unroll
        for (int i = 0; i < 4; i++) {
            float va = (i == 0) ? av.x : (i == 1) ? av.y : (i == 2) ? av.z : av.w;
            float vb = (i == 0) ? bv.x : (i == 1) ? bv.y : (i == 2) ? bv.z : bv.w;
            *(float2*)&Aa[(4 * lac + i) * 128 + 2 * lam] = make_float2(va, va);
            *(float2*)&Ab[(4 * lac + i) * 128 + 2 * lam] = make_float2(vb, vb);
        }
        // store B direct
        *(float4*)&Bx[lbk * 64 + 4 * lbc] = xv;
        *(float4*)&Bj[lbk * 64 + 4 * lbc] = jv;
        __syncthreads();

        #pragma unroll
        for (int k = 0; k < 16; k++) {
            ulonglong2 Aa01 = *(const ulonglong2*)&Aa[k * 128 + 8 * ty];
            ulonglong2 Aa23 = *(const ulonglong2*)&Aa[k * 128 + 8 * ty + 4];
            ulonglong2 Ab01 = *(const ulonglong2*)&Ab[k * 128 + 8 * ty];
            ulonglong2 Ab23 = *(const ulonglong2*)&Ab[k * 128 + 8 * ty + 4];
            ulonglong2 X   = *(const ulonglong2*)&Bx[k * 64 + 4 * tx];
            ulonglong2 J   = *(const ulonglong2*)&Bj[k * 64 + 4 * tx];
            ffma2(acc[0][0], Aa01.x, X.x); ffma2(acc[0][1], Aa01.x, X.y);
            ffma2(acc[1][0], Aa01.y, X.x); ffma2(acc[1][1], Aa01.y, X.y);
            ffma2(acc[2][0], Aa23.x, X.x); ffma2(acc[2][1], Aa23.x, X.y);
            ffma2(acc[3][0], Aa23.y, X.x); ffma2(acc[3][1], Aa23.y, X.y);
            ffma2(acc[0][0], Ab01.x, J.x); ffma2(acc[0][1], Ab01.x, J.y);
            ffma2(acc[1][0], Ab01.y, J.x); ffma2(acc[1][1], Ab01.y, J.y);
            ffma2(acc[2][0], Ab23.x, J.x); ffma2(acc[2][1], Ab23.x, J.y);
            ffma2(acc[3][0], Ab23.y, J.x); ffma2(acc[3][1], Ab23.y, J.y);
        }
    }

    // write negated partials
    #pragma unroll
    for (int mi = 0; mi < 4; mi++) {
        float2 u0 = upk(acc[mi][0]);
        float2 u1 = upk(acc[mi][1]);
        int m = ty * 4 + mi;
        *(float4*)&g_F2[((size_t)blockIdx.y * NM + m) * G2_PPAD + p0 + 4 * tx] =
            make_float4(-u0.x, -u0.y, -u1.x, -u1.y);
    }
}

// ---------------- final: reduce partials, scale by xs^3, scatter forces ----------------
__global__ void final_kernel(const float* __restrict__ Rs, float* __restrict__ out) {
    __shared__ float Fxs[NP];
    __shared__ float ssa;
    const int m = blockIdx.x;
    const int tid = threadIdx.x;

    if (tid == 0) {
        float s = 0.0f;
        for (int b = 0; b < G1_BLOCKS; b++) s += g_sa[b * NM + m];
        ssa = s;
    }
    if (tid == 32) {
        float e = 0.0f;
        for (int b = 0; b < G1_BLOCKS; b++) e += g_Ep[b * NM + m];
        out[m] = e / QV;     // Es (STD=1, C=0)
    }
    __syncthreads();

    if (tid < NP) {
        float F = ssa * g_qxs[m * NP + tid];
        for (int ks = 0; ks < G2_KS; ks++)
            F += g_F2[((size_t)ks * NM + m) * G2_PPAD + tid];
        Fxs[tid] = F * g_xs3[m * NP + tid];
    }
    __syncthreads();

    if (tid < NA * 3) {
        int a = tid / 3, c = tid % 3;
        float Ra = Rs[(m * NA + a) * 3 + c];
        float acc = 0.0f;
        #pragma unroll
        for (int bb = 0; bb < NA; bb++) {
            if (bb == a) continue;
            int hi = (a > bb) ? a : bb;
            int lo = (a > bb) ? bb : a;
            int p = hi * (hi - 1) / 2 + lo;
            float Rb = Rs[(m * NA + bb) * 3 + c];
            acc += (Rb - Ra) * Fxs[p];
        }
        out[NM + m * NA * 3 + tid] = acc;
    }
}

extern "C" void kernel_launch(void* const* d_in, const int* in_sizes, int n_in,
                              void* d_out, int out_size) {
    const float* Rs = (const float*)d_in[0];        // [64, 24, 3]
    const float* xs_train = (const float*)d_in[1];  // [6000, 276]
    const float* Jx = (const float*)d_in[2];        // [6000, 276]
    float* out = (float*)d_out;

    prep1_kernel<<<NM, 288>>>(Rs);
    prep2_kernel<<<NTPAD / 8, 256>>>(xs_train, Jx);
    gemm1_kernel<<<G1_BLOCKS, 256>>>(xs_train, Jx);
    gemm2_kernel<<<dim3(G2_PT, G2_KS), 256>>>(xs_train, Jx);
    final_kernel<<<NM, 288>>>(Rs, out);
}